// round 1
// baseline (speedup 1.0000x reference)
#include <cuda_runtime.h>
#include <cuda_bf16.h>

// Problem constants
#define B_   32
#define CIN_ 256
#define COUT_ 256
#define H_   64
#define W_   64
#define OH_  32
#define OW_  32
// mask from _build_crop_mask(64,32,32,4,0) is all-True (start_idx=1560 > L=1024),
// so this is a plain stride-2 pad-1 3x3 conv.

// Pre-transposed weights: [9][CIN][COUT]  (khw, cin, cout)
__device__ float g_wT[9 * CIN_ * COUT_];

__global__ void weight_transform_kernel(const float* __restrict__ w) {
    // w: [COUT][CIN][3][3] -> g_wT[p][cin][cout]
    int idx = blockIdx.x * blockDim.x + threadIdx.x;
    const int total = COUT_ * CIN_ * 9;
    if (idx >= total) return;
    // idx over (p, cin, cout) for coalesced WRITES
    int cout = idx % COUT_;
    int t = idx / COUT_;
    int cin = t % CIN_;
    int p = t / CIN_;
    g_wT[idx] = w[cout * (CIN_ * 9) + cin * 9 + p];
}

#define BM 128
#define BN 128
#define BK 8
#define TM 8
#define TN 8

__global__ __launch_bounds__(256, 2)
void conv_gemm_kernel(const float* __restrict__ x, float* __restrict__ out) {
    // GEMM: C[m][n] = sum_k wT[k][m] * X_im2col[k][n]
    // m = cout (256), n = b*1024 + oh*32 + ow (32768), k = p*256 + cin (2304)
    __shared__ float As[BK][BM];
    __shared__ float Bs[BK][BN];

    const int tid = threadIdx.x;
    const int tx = tid & 15;       // 0..15 -> n micro
    const int ty = tid >> 4;       // 0..15 -> m micro
    const int lcol = tid & 127;    // load column (0..127)
    const int lrow0 = tid >> 7;    // load row base (0..1)

    const int n0 = blockIdx.x * BN;     // pixel-global tile start
    const int m0 = blockIdx.y * BM;     // cout tile start
    const int b = n0 >> 10;             // n0 / 1024 (BN=128 divides 1024)
    const int pix0 = n0 & 1023;

    // This thread's B-load pixel (fixed across whole kernel)
    const int pix = pix0 + lcol;
    const int oh = pix >> 5;
    const int ow = pix & 31;
    const int ih_base = oh * 2 - 1;
    const int iw_base = ow * 2 - 1;

    const float* xb = x + (size_t)b * CIN_ * H_ * W_;

    float acc[TM][TN];
#pragma unroll
    for (int i = 0; i < TM; ++i)
#pragma unroll
        for (int j = 0; j < TN; ++j) acc[i][j] = 0.0f;

#pragma unroll 1
    for (int p = 0; p < 9; ++p) {
        const int kh = p / 3;
        const int kw = p - kh * 3;
        const int ih = ih_base + kh;
        const int iw = iw_base + kw;
        const bool valid = ((unsigned)ih < (unsigned)H_) && ((unsigned)iw < (unsigned)W_);
        const int ihiw = valid ? (ih * W_ + iw) : 0;
        const float* wp = g_wT + p * (CIN_ * COUT_) + m0;

#pragma unroll 1
        for (int cin0 = 0; cin0 < CIN_; cin0 += BK) {
            __syncthreads();
            // Load A tile: As[k][m] = wT[p][cin0+k][m0+lcol]  (coalesced)
#pragma unroll
            for (int j = 0; j < 4; ++j) {
                int kr = lrow0 + j * 2;
                As[kr][lcol] = wp[(cin0 + kr) * COUT_ + lcol];
            }
            // Load B tile: Bs[k][n] = x[b][cin0+k][ih][iw] or 0
#pragma unroll
            for (int j = 0; j < 4; ++j) {
                int kr = lrow0 + j * 2;
                float v = 0.0f;
                if (valid) v = xb[(size_t)(cin0 + kr) * (H_ * W_) + ihiw];
                Bs[kr][lcol] = v;
            }
            __syncthreads();

#pragma unroll
            for (int kk = 0; kk < BK; ++kk) {
                float a[TM], bv[TN];
#pragma unroll
                for (int i = 0; i < TM; ++i) a[i] = As[kk][ty * TM + i];
#pragma unroll
                for (int j = 0; j < TN; ++j) bv[j] = Bs[kk][tx * TN + j];
#pragma unroll
                for (int i = 0; i < TM; ++i)
#pragma unroll
                    for (int j = 0; j < TN; ++j)
                        acc[i][j] = fmaf(a[i], bv[j], acc[i][j]);
            }
        }
    }

    // Write out: out[b][cout][pix]  (out layout [B][COUT][OH][OW])
#pragma unroll
    for (int i = 0; i < TM; ++i) {
        const int cout = m0 + ty * TM + i;
        float* op = out + ((size_t)b * COUT_ + cout) * (OH_ * OW_) + pix0 + tx * TN;
#pragma unroll
        for (int j = 0; j < TN; ++j) op[j] = acc[i][j];
    }
}

extern "C" void kernel_launch(void* const* d_in, const int* in_sizes, int n_in,
                              void* d_out, int out_size) {
    const float* x = (const float*)d_in[0];        // [32,256,64,64]
    const float* w = (const float*)d_in[1];        // [256,256,3,3]
    float* out = (float*)d_out;                    // [32,256,32,32]

    {
        const int total = COUT_ * CIN_ * 9;
        weight_transform_kernel<<<(total + 255) / 256, 256>>>(w);
    }
    {
        dim3 grid((B_ * OH_ * OW_) / BN, COUT_ / BM);  // (256, 2)
        conv_gemm_kernel<<<grid, 256>>>(x, out);
    }
}

// round 3
// speedup vs baseline: 1.6617x; 1.6617x over previous
#include <cuda_runtime.h>
#include <cuda_bf16.h>
#include <cstdint>

// ---------------------------------------------------------------------------
// B=32, CIN=256, COUT=256, 64x64 -> 32x32, 3x3 stride2 pad1 conv. Crop mask is
// all-True => plain conv. tcgen05 unavailable (ptxas target = plain sm_103),
// so: implicit GEMM on mma.sync bf16 with split precision:
//   fp32 v = hi + lo (bf16);  C = Ahi*Bhi + Alo*Bhi + Ahi*Blo  (fp32 acc)
// encoded as ONE bf16 GEMM with K' = 3*2304 = 6912:
//   A'[p][cout][ hi(256) | lo(256) | hi(256) ]
//   B  k-tiles map to X'[b][s][ hi(256) | lo(256) ] via per-ktile offset.
// ---------------------------------------------------------------------------

#define B_    32
#define CIN_  256
#define COUT_ 256
#define H_    64
#define W_    64
#define HW_   4096
#define NPIX_ 1024

#define BM 128
#define BN 256
#define KT 64              // bf16 k per tile
#define KPP 768            // k' per p (3 segments x 256)
#define NIT 108            // 9 p * 12 ktiles

#define STAGE_BYTES 49152  // A 16KB + B 32KB
#define B_OFF 16384
#define SMEM_TOTAL (3 * STAGE_BYTES)

__device__ __align__(128) __nv_bfloat16 g_A2[9 * COUT_ * KPP];   // 3.5 MB
__device__ __align__(128) __nv_bfloat16 g_X2[B_ * HW_ * 512];    // 134 MB

// ---------------------------------------------------------------------------
__device__ __forceinline__ uint32_t smem_u32(const void* p) {
    uint32_t a;
    asm("{ .reg .u64 t; cvta.to.shared.u64 t, %1; cvt.u32.u64 %0, t; }" : "=r"(a) : "l"(p));
    return a;
}
__device__ __forceinline__ void cp16(uint32_t dst, const void* src, int sz) {
    asm volatile("cp.async.cg.shared.global [%0], [%1], 16, %2;"
                 :: "r"(dst), "l"(src), "r"(sz) : "memory");
}
__device__ __forceinline__ void cp_commit() {
    asm volatile("cp.async.commit_group;" ::: "memory");
}
__device__ __forceinline__ void ldm4(uint32_t* r, uint32_t addr) {
    asm volatile("ldmatrix.sync.aligned.m8n8.x4.shared.b16 {%0,%1,%2,%3}, [%4];"
                 : "=r"(r[0]), "=r"(r[1]), "=r"(r[2]), "=r"(r[3]) : "r"(addr));
}
__device__ __forceinline__ void mma_bf16(float* d, const uint32_t* a, uint32_t b0, uint32_t b1) {
    asm volatile(
        "mma.sync.aligned.m16n8k16.row.col.f32.bf16.bf16.f32 "
        "{%0,%1,%2,%3}, {%4,%5,%6,%7}, {%8,%9}, {%0,%1,%2,%3};"
        : "+f"(d[0]), "+f"(d[1]), "+f"(d[2]), "+f"(d[3])
        : "r"(a[0]), "r"(a[1]), "r"(a[2]), "r"(a[3]), "r"(b0), "r"(b1));
}

// ---------------------------------------------------------------------------
// Prologues
// ---------------------------------------------------------------------------
__global__ void weight_transform_kernel(const float* __restrict__ w) {
    int idx = blockIdx.x * blockDim.x + threadIdx.x;
    const int total = 9 * COUT_ * KPP;
    if (idx >= total) return;
    int k = idx % KPP;
    int t = idx / KPP;
    int cout = t & 255;
    int p = t >> 8;
    int cin = k & 255;
    int seg = k >> 8;                       // 0:hi 1:lo 2:hi
    float v = w[cout * (CIN_ * 9) + cin * 9 + p];
    __nv_bfloat16 hi = __float2bfloat16(v);
    g_A2[idx] = (seg == 1) ? __float2bfloat16(v - __bfloat162float(hi)) : hi;
}

// x[b][cin][h][w] f32 -> X'[b][s][cin]=hi, [256+cin]=lo
__global__ void x_transform_kernel(const float* __restrict__ x) {
    __shared__ float tile[32][33];
    int b = blockIdx.z, c0 = blockIdx.y * 32, s0 = blockIdx.x * 32;
    int tx = threadIdx.x, ty = threadIdx.y;          // 32 x 8
    const float* xb = x + ((size_t)b * CIN_ + c0) * HW_ + s0;
#pragma unroll
    for (int k = 0; k < 4; ++k)
        tile[ty + 8 * k][tx] = xb[(size_t)(ty + 8 * k) * HW_ + tx];
    __syncthreads();
#pragma unroll
    for (int k = 0; k < 4; ++k) {
        float v = tile[tx][ty + 8 * k];
        __nv_bfloat16 hi = __float2bfloat16(v);
        size_t o = ((size_t)b * HW_ + s0 + ty + 8 * k) * 512 + c0 + tx;
        g_X2[o] = hi;
        g_X2[o + 256] = __float2bfloat16(v - __bfloat162float(hi));
    }
}

// ---------------------------------------------------------------------------
// Main HMMA implicit-GEMM kernel. grid (2, 128), 256 threads.
// ---------------------------------------------------------------------------
__global__ void __launch_bounds__(256, 1) conv_hmma_kernel(float* __restrict__ out) {
    extern __shared__ char smem[];
    const uint32_t sb = smem_u32(smem);
    const int tid = threadIdx.x;
    const int lane = tid & 31, warp = tid >> 5;
    const int m0 = blockIdx.x * BM;
    const int n0 = blockIdx.y * BN;
    const int b = n0 >> 10;
    const int pix0 = n0 & (NPIX_ - 1);

    // ---- loader thread mapping ----
    const int aRow = tid >> 1;            // A tile row (m), 0..127
    const int aC = (tid & 1) * 4;         // starting 16B chunk
    const int aSwz = aRow & 7;
    const uint32_t aDst0 = sb + aRow * 128;
    const int pixL = pix0 + tid;          // B tile row = pixel
    const int ohL = pixL >> 5, owL = pixL & 31;
    const int bSwz = tid & 7;
    const uint32_t bDst0 = sb + B_OFF + tid * 128;
    const __nv_bfloat16* gA0 = g_A2 + (size_t)(m0 + aRow) * KPP + aC * 8;
    const __nv_bfloat16* gX0 = g_X2 + (size_t)b * HW_ * 512;

    // load iterator state
    int lp = 0, lkt = 0, lkh = 0, lkw = 0;

    auto load_stage = [&](int stage) {
        const uint32_t st = stage * STAGE_BYTES;
        const char* gA = (const char*)(gA0 + (size_t)lp * (COUT_ * KPP) + lkt * KT);
#pragma unroll
        for (int j = 0; j < 4; ++j)
            cp16(aDst0 + st + (((aC + j) ^ aSwz) << 4), gA + j * 16, 16);
        const int ih = ohL * 2 - 1 + lkh;
        const int iw = owL * 2 - 1 + lkw;
        const bool v = ((unsigned)ih < (unsigned)H_) && ((unsigned)iw < (unsigned)W_);
        const int bo = ((lkt >= 8) ? 256 : 0) + (lkt & 3) * KT;
        const char* gB = (const char*)(gX0 + (size_t)(v ? (ih * W_ + iw) : 0) * 512 + bo);
        const int sz = v ? 16 : 0;
#pragma unroll
        for (int j = 0; j < 8; ++j)
            cp16(bDst0 + st + ((j ^ bSwz) << 4), gB + j * 16, sz);
        cp_commit();
    };
    auto adv = [&]() {
        if (++lkt == 12) { lkt = 0; ++lp; if (++lkw == 3) { lkw = 0; ++lkh; } }
    };

    float acc[4][8][4];
#pragma unroll
    for (int mi = 0; mi < 4; ++mi)
#pragma unroll
        for (int ni = 0; ni < 8; ++ni)
#pragma unroll
            for (int j = 0; j < 4; ++j) acc[mi][ni][j] = 0.0f;

    load_stage(0); adv();
    load_stage(1); adv();

    // ---- compute warp mapping ----
    const int mw = (warp >> 2) * 64;      // 0 or 64
    const int nw = (warp & 3) * 64;       // 0,64,128,192
    const int lr = lane & 15;
    const int lc = lane >> 4;

#pragma unroll 1
    for (int it = 0; it < NIT; ++it) {
        if (it + 2 < NIT) { load_stage((it + 2) % 3); adv(); }
        else cp_commit();
        asm volatile("cp.async.wait_group 2;" ::: "memory");
        __syncthreads();
        const uint32_t st = sb + (it % 3) * STAGE_BYTES;
#pragma unroll
        for (int k16 = 0; k16 < 4; ++k16) {
            uint32_t a[4][4], bb[4][4];
#pragma unroll
            for (int mi = 0; mi < 4; ++mi) {
                int row = mw + mi * 16 + lr;
                ldm4(a[mi], st + row * 128 + (((k16 * 2 + lc) ^ (row & 7)) << 4));
            }
#pragma unroll
            for (int g = 0; g < 4; ++g) {
                int row = nw + g * 16 + lr;
                ldm4(bb[g], st + B_OFF + row * 128 + (((k16 * 2 + lc) ^ (row & 7)) << 4));
            }
#pragma unroll
            for (int mi = 0; mi < 4; ++mi)
#pragma unroll
                for (int ni = 0; ni < 8; ++ni)
                    mma_bf16(acc[mi][ni], a[mi], bb[ni >> 1][ni & 1], bb[ni >> 1][(ni & 1) + 2]);
        }
        __syncthreads();
    }

    // ---- epilogue ----
    const int er = lane >> 2;             // 0..7
    const int ec = (lane & 3) * 2;
    float* ob = out + (size_t)b * COUT_ * NPIX_;
#pragma unroll
    for (int mi = 0; mi < 4; ++mi) {
        const int cout0 = m0 + mw + mi * 16 + er;
#pragma unroll
        for (int ni = 0; ni < 8; ++ni) {
            const int nc = pix0 + nw + ni * 8 + ec;
            float2* p0 = (float2*)(ob + (size_t)cout0 * NPIX_ + nc);
            float2* p1 = (float2*)(ob + (size_t)(cout0 + 8) * NPIX_ + nc);
            *p0 = make_float2(acc[mi][ni][0], acc[mi][ni][1]);
            *p1 = make_float2(acc[mi][ni][2], acc[mi][ni][3]);
        }
    }
}

// ---------------------------------------------------------------------------
extern "C" void kernel_launch(void* const* d_in, const int* in_sizes, int n_in,
                              void* d_out, int out_size) {
    const float* x = (const float*)d_in[0];   // [32,256,64,64]
    const float* w = (const float*)d_in[1];   // [256,256,3,3]
    float* out = (float*)d_out;               // [32,256,32,32]

    cudaFuncSetAttribute(conv_hmma_kernel,
                         cudaFuncAttributeMaxDynamicSharedMemorySize, SMEM_TOTAL);

    {
        const int total = 9 * COUT_ * KPP;
        weight_transform_kernel<<<(total + 255) / 256, 256>>>(w);
    }
    {
        dim3 blk(32, 8);
        dim3 grd(HW_ / 32, CIN_ / 32, B_);
        x_transform_kernel<<<grd, blk>>>(x);
    }
    {
        dim3 grid(COUT_ / BM, (B_ * NPIX_) / BN);   // (2, 128)
        conv_hmma_kernel<<<grid, 256, SMEM_TOTAL>>>(out);
    }
}

// round 4
// speedup vs baseline: 2.3815x; 1.4332x over previous
#include <cuda_runtime.h>
#include <cuda_bf16.h>
#include <cstdint>

// ---------------------------------------------------------------------------
// B=32, CIN=256, COUT=256, 64x64 -> 32x32, 3x3 stride2 pad1 conv.
// Crop mask is all-True => plain conv. tcgen05 unavailable (plain sm_103
// ptxas target), so: single-pass TF32 implicit GEMM on mma.sync.m16n8k8.
// Operands rounded with cvt.rna.tf32.f32 -> rel_err ~2-4e-4.
//   M = COUT (256), N = B*1024 (32768), K = 9*256 (2304)
// ---------------------------------------------------------------------------

#define B_    32
#define CIN_  256
#define COUT_ 256
#define H_    64
#define W_    64
#define HW_   4096
#define NPIX_ 1024

#define BM 128
#define BN 256
#define KC 64
#define NIT 36                 // 9 taps * 4 cin-chunks

// SMEM: A tile 128 x 64 f32, row stride 68 floats (272B, conflict-free LDS)
//       B tile 256 x 64 f32, row stride 68 floats
#define A_ROW_B   272
#define A_TILE_B  (128 * A_ROW_B)          // 34816
#define B_ROW_B   272
#define B_TILE_B  (256 * B_ROW_B)          // 69632
#define STAGE_B   (A_TILE_B + B_TILE_B)    // 104448
#define OFF_B     A_TILE_B
#define SMEM_TOTAL (2 * STAGE_B)           // 208896

// tf32-rounded operand planes (device globals; no runtime allocation)
__device__ __align__(128) float g_A3[9 * COUT_ * CIN_];      // [p][cout][cin]  2.36MB
__device__ __align__(128) float g_Xf[(size_t)B_ * HW_ * CIN_]; // [b][s][cin]  134MB

// ---------------------------------------------------------------------------
__device__ __forceinline__ uint32_t smem_u32(const void* p) {
    uint32_t a;
    asm("{ .reg .u64 t; cvta.to.shared.u64 t, %1; cvt.u32.u64 %0, t; }" : "=r"(a) : "l"(p));
    return a;
}
__device__ __forceinline__ void cp16(uint32_t dst, const void* src, int sz) {
    asm volatile("cp.async.cg.shared.global [%0], [%1], 16, %2;"
                 :: "r"(dst), "l"(src), "r"(sz) : "memory");
}
__device__ __forceinline__ void cp_commit() {
    asm volatile("cp.async.commit_group;" ::: "memory");
}
__device__ __forceinline__ uint32_t f2tf32(float v) {
    uint32_t r;
    asm("cvt.rna.tf32.f32 %0, %1;" : "=r"(r) : "f"(v));
    return r;
}
__device__ __forceinline__ void mma_tf32(float* d, const uint32_t* a, uint32_t b0, uint32_t b1) {
    asm volatile(
        "mma.sync.aligned.m16n8k8.row.col.f32.tf32.tf32.f32 "
        "{%0,%1,%2,%3}, {%4,%5,%6,%7}, {%8,%9}, {%0,%1,%2,%3};"
        : "+f"(d[0]), "+f"(d[1]), "+f"(d[2]), "+f"(d[3])
        : "r"(a[0]), "r"(a[1]), "r"(a[2]), "r"(a[3]), "r"(b0), "r"(b1));
}
__device__ __forceinline__ uint32_t lds32(uint32_t addr) {
    uint32_t v;
    asm volatile("ld.shared.b32 %0, [%1];" : "=r"(v) : "r"(addr));
    return v;
}

// ---------------------------------------------------------------------------
// Prologues
// ---------------------------------------------------------------------------
__global__ void weight_transform_kernel(const float* __restrict__ w) {
    int idx = blockIdx.x * blockDim.x + threadIdx.x;
    const int total = 9 * COUT_ * CIN_;
    if (idx >= total) return;
    int cin = idx & 255;
    int cout = (idx >> 8) & 255;
    int p = idx >> 16;
    float v = w[cout * (CIN_ * 9) + cin * 9 + p];
    ((uint32_t*)g_A3)[idx] = f2tf32(v);
}

// x[b][cin][h][w] f32 -> g_Xf[b][s=h*64+w][cin] (tf32-rounded)
__global__ void x_transform_kernel(const float* __restrict__ x) {
    __shared__ float tile[32][33];
    int b = blockIdx.z, c0 = blockIdx.y * 32, s0 = blockIdx.x * 32;
    int tx = threadIdx.x, ty = threadIdx.y;        // 32 x 8
    const float* xb = x + ((size_t)b * CIN_ + c0) * HW_ + s0;
#pragma unroll
    for (int k = 0; k < 4; ++k)
        tile[ty + 8 * k][tx] = xb[(size_t)(ty + 8 * k) * HW_ + tx];
    __syncthreads();
#pragma unroll
    for (int k = 0; k < 4; ++k) {
        float v = tile[tx][ty + 8 * k];
        size_t o = ((size_t)b * HW_ + s0 + ty + 8 * k) * CIN_ + c0 + tx;
        ((uint32_t*)g_Xf)[o] = f2tf32(v);
    }
}

// ---------------------------------------------------------------------------
// Main TF32 implicit-GEMM kernel. grid (2, 128), 256 threads (8 warps).
// ---------------------------------------------------------------------------
__global__ void __launch_bounds__(256, 1) conv_tf32_kernel(float* __restrict__ out) {
    extern __shared__ char smem[];
    const uint32_t sb = smem_u32(smem);
    const int tid = threadIdx.x;
    const int lane = tid & 31, warp = tid >> 5;
    const int m0 = blockIdx.x * BM;
    const int n0 = blockIdx.y * BN;
    const int b = n0 >> 10;
    const int pix0 = n0 & (NPIX_ - 1);

    // ---- loader mapping ----
    const int aRow = tid >> 1;            // 0..127
    const int aHalf = (tid & 1) * 8;      // chunk base (16B chunks, 16 per row)
    const uint32_t aDst0 = sb + aRow * A_ROW_B + aHalf * 16;
    const int pixL = pix0 + tid;
    const int ohL = pixL >> 5, owL = pixL & 31;
    const uint32_t bDst0 = sb + OFF_B + tid * B_ROW_B;
    const float* gA0 = g_A3 + (size_t)(m0 + aRow) * CIN_ + aHalf * 4;
    const float* gX0 = g_Xf + (size_t)b * HW_ * CIN_;

    auto load_stage = [&](int buf, int s) {
        const int p = s >> 2;
        const int cin0 = (s & 3) * KC;
        const int kh = p / 3, kw = p - kh * 3;
        const uint32_t st = buf * STAGE_B;
        const char* gA = (const char*)(gA0 + (size_t)p * (COUT_ * CIN_) + cin0);
#pragma unroll
        for (int j = 0; j < 8; ++j)
            cp16(aDst0 + st + j * 16, gA + j * 16, 16);
        const int ih = ohL * 2 - 1 + kh;
        const int iw = owL * 2 - 1 + kw;
        const bool v = ((unsigned)ih < (unsigned)H_) && ((unsigned)iw < (unsigned)W_);
        const char* gB = (const char*)(gX0 + (size_t)(v ? (ih * W_ + iw) : 0) * CIN_ + cin0);
        const int sz = v ? 16 : 0;
#pragma unroll
        for (int j = 0; j < 16; ++j)
            cp16(bDst0 + st + j * 16, gB + j * 16, sz);
        cp_commit();
    };

    float acc[4][8][4];
#pragma unroll
    for (int mi = 0; mi < 4; ++mi)
#pragma unroll
        for (int ni = 0; ni < 8; ++ni)
#pragma unroll
            for (int j = 0; j < 4; ++j) acc[mi][ni][j] = 0.0f;

    load_stage(0, 0);
    load_stage(1, 1);

    // ---- compute mapping ----
    const int mw = (warp >> 2) * 64;      // 0 / 64
    const int nw = (warp & 3) * 64;       // 0..192
    const int lg = lane >> 2;             // 0..7 (row group)
    const int lc = lane & 3;              // 0..3 (col in quad)

#pragma unroll 1
    for (int it = 0; it < NIT; ++it) {
        asm volatile("cp.async.wait_group 1;" ::: "memory");
        __syncthreads();
        const uint32_t st = sb + (it & 1) * STAGE_B;
        const uint32_t stB = st + OFF_B;
#pragma unroll
        for (int ks = 0; ks < 8; ++ks) {
            const uint32_t kbyte = (uint32_t)(ks * 8 + lc) * 4;
            uint32_t a[4][4];
#pragma unroll
            for (int mi = 0; mi < 4; ++mi) {
                const uint32_t r0 = st + (mw + mi * 16 + lg) * A_ROW_B + kbyte;
                a[mi][0] = lds32(r0);
                a[mi][1] = lds32(r0 + 8 * A_ROW_B);
                a[mi][2] = lds32(r0 + 16);
                a[mi][3] = lds32(r0 + 8 * A_ROW_B + 16);
            }
#pragma unroll
            for (int ni = 0; ni < 8; ++ni) {
                const uint32_t r0 = stB + (nw + ni * 8 + lg) * B_ROW_B + kbyte;
                uint32_t b0 = lds32(r0);
                uint32_t b1 = lds32(r0 + 16);
#pragma unroll
                for (int mi = 0; mi < 4; ++mi)
                    mma_tf32(acc[mi][ni], a[mi], b0, b1);
            }
        }
        __syncthreads();
        if (it + 2 < NIT) load_stage(it & 1, it + 2);
        else cp_commit();
    }

    // ---- epilogue: c frag (row = lg, col = lc*2 {+1}; rows +8 for c2/c3) ----
    float* ob = out + (size_t)b * COUT_ * NPIX_;
#pragma unroll
    for (int mi = 0; mi < 4; ++mi) {
        const int cout0 = m0 + mw + mi * 16 + lg;
#pragma unroll
        for (int ni = 0; ni < 8; ++ni) {
            const int nc = pix0 + nw + ni * 8 + lc * 2;
            float2* p0 = (float2*)(ob + (size_t)cout0 * NPIX_ + nc);
            float2* p1 = (float2*)(ob + (size_t)(cout0 + 8) * NPIX_ + nc);
            *p0 = make_float2(acc[mi][ni][0], acc[mi][ni][1]);
            *p1 = make_float2(acc[mi][ni][2], acc[mi][ni][3]);
        }
    }
}

// ---------------------------------------------------------------------------
extern "C" void kernel_launch(void* const* d_in, const int* in_sizes, int n_in,
                              void* d_out, int out_size) {
    const float* x = (const float*)d_in[0];   // [32,256,64,64]
    const float* w = (const float*)d_in[1];   // [256,256,3,3]
    float* out = (float*)d_out;               // [32,256,32,32]

    cudaFuncSetAttribute(conv_tf32_kernel,
                         cudaFuncAttributeMaxDynamicSharedMemorySize, SMEM_TOTAL);

    {
        const int total = 9 * COUT_ * CIN_;
        weight_transform_kernel<<<(total + 255) / 256, 256>>>(w);
    }
    {
        dim3 blk(32, 8);
        dim3 grd(HW_ / 32, CIN_ / 32, B_);
        x_transform_kernel<<<grd, blk>>>(x);
    }
    {
        dim3 grid(COUT_ / BM, (B_ * NPIX_) / BN);   // (2, 128)
        conv_tf32_kernel<<<grid, 256, SMEM_TOTAL>>>(out);
    }
}

// round 5
// speedup vs baseline: 3.5486x; 1.4901x over previous
#include <cuda_runtime.h>
#include <cuda_bf16.h>
#include <cstdint>

// ---------------------------------------------------------------------------
// B=32, CIN=256, COUT=256, 64x64 -> 32x32, 3x3 stride2 pad1 conv. Crop mask
// all-True => plain conv. TF32 implicit GEMM on mma.sync.m16n8k8.
// Round 5: loads via cp.async.bulk (256B/row, 16x fewer load instructions),
// mbarrier complete_tx double-buffered pipeline.
// ---------------------------------------------------------------------------

#define B_    32
#define CIN_  256
#define COUT_ 256
#define H_    64
#define W_    64
#define HW_   4096
#define NPIX_ 1024

#define BM 128
#define BN 256
#define KC 64
#define NIT 36                 // 9 taps * 4 cin-chunks

// Rows are 256B payload at 272B stride (16B aligned, conflict-free LDS)
#define A_ROW_B   272
#define A_TILE_B  (128 * A_ROW_B)          // 34816
#define B_ROW_B   272
#define B_TILE_B  (256 * B_ROW_B)          // 69632
#define STAGE_B   (A_TILE_B + B_TILE_B)    // 104448
#define OFF_B     A_TILE_B
#define TILES_OFF 1024
#define SMEM_TOTAL (TILES_OFF + 2 * STAGE_B)   // 209920
#define MBAR0_OFF 0
#define MBAR1_OFF 16

__device__ __align__(128) float g_A3[9 * COUT_ * CIN_];        // [p][cout][cin]
__device__ __align__(128) float g_Xf[(size_t)B_ * HW_ * CIN_]; // [b][s][cin]

// ---------------------------------------------------------------------------
__device__ __forceinline__ uint32_t smem_u32(const void* p) {
    uint32_t a;
    asm("{ .reg .u64 t; cvta.to.shared.u64 t, %1; cvt.u32.u64 %0, t; }" : "=r"(a) : "l"(p));
    return a;
}
__device__ __forceinline__ void bulk_g2s(uint32_t dst, const void* src, uint32_t bytes,
                                         uint32_t mbar) {
    asm volatile(
        "cp.async.bulk.shared::cluster.global.mbarrier::complete_tx::bytes "
        "[%0], [%1], %2, [%3];"
        :: "r"(dst), "l"(src), "r"(bytes), "r"(mbar) : "memory");
}
__device__ __forceinline__ void mbar_init(uint32_t a, uint32_t cnt) {
    asm volatile("mbarrier.init.shared.b64 [%0], %1;" :: "r"(a), "r"(cnt) : "memory");
}
__device__ __forceinline__ void mbar_expect_tx(uint32_t a, uint32_t tx) {
    asm volatile("mbarrier.arrive.expect_tx.shared.b64 _, [%0], %1;"
                 :: "r"(a), "r"(tx) : "memory");
}
__device__ __forceinline__ void mbar_wait(uint32_t a, uint32_t parity) {
    asm volatile(
        "{\n\t.reg .pred P1;\n\t"
        "W_%=:\n\t"
        "mbarrier.try_wait.parity.acquire.cta.shared::cta.b64 P1, [%0], %1, 0x989680;\n\t"
        "@!P1 bra W_%=;\n\t}"
        :: "r"(a), "r"(parity) : "memory");
}
__device__ __forceinline__ uint32_t f2tf32(float v) {
    uint32_t r;
    asm("cvt.rna.tf32.f32 %0, %1;" : "=r"(r) : "f"(v));
    return r;
}
__device__ __forceinline__ void mma_tf32(float* d, const uint32_t* a, uint32_t b0, uint32_t b1) {
    asm volatile(
        "mma.sync.aligned.m16n8k8.row.col.f32.tf32.tf32.f32 "
        "{%0,%1,%2,%3}, {%4,%5,%6,%7}, {%8,%9}, {%0,%1,%2,%3};"
        : "+f"(d[0]), "+f"(d[1]), "+f"(d[2]), "+f"(d[3])
        : "r"(a[0]), "r"(a[1]), "r"(a[2]), "r"(a[3]), "r"(b0), "r"(b1));
}
__device__ __forceinline__ uint32_t lds32(uint32_t addr) {
    uint32_t v;
    asm volatile("ld.shared.b32 %0, [%1];" : "=r"(v) : "r"(addr));
    return v;
}

// ---------------------------------------------------------------------------
// Prologues
// ---------------------------------------------------------------------------
__global__ void weight_transform_kernel(const float* __restrict__ w) {
    int idx = blockIdx.x * blockDim.x + threadIdx.x;
    const int total = 9 * COUT_ * CIN_;
    if (idx >= total) return;
    int cin = idx & 255;
    int cout = (idx >> 8) & 255;
    int p = idx >> 16;
    float v = w[cout * (CIN_ * 9) + cin * 9 + p];
    ((uint32_t*)g_A3)[idx] = f2tf32(v);
}

__global__ void x_transform_kernel(const float* __restrict__ x) {
    __shared__ float tile[32][33];
    int b = blockIdx.z, c0 = blockIdx.y * 32, s0 = blockIdx.x * 32;
    int tx = threadIdx.x, ty = threadIdx.y;        // 32 x 8
    const float* xb = x + ((size_t)b * CIN_ + c0) * HW_ + s0;
#pragma unroll
    for (int k = 0; k < 4; ++k)
        tile[ty + 8 * k][tx] = xb[(size_t)(ty + 8 * k) * HW_ + tx];
    __syncthreads();
#pragma unroll
    for (int k = 0; k < 4; ++k) {
        float v = tile[tx][ty + 8 * k];
        size_t o = ((size_t)b * HW_ + s0 + ty + 8 * k) * CIN_ + c0 + tx;
        ((uint32_t*)g_Xf)[o] = f2tf32(v);
    }
}

// ---------------------------------------------------------------------------
// Main TF32 implicit-GEMM. grid (2, 128), 256 threads (8 warps).
// ---------------------------------------------------------------------------
__global__ void __launch_bounds__(256, 1) conv_tf32_kernel(float* __restrict__ out) {
    extern __shared__ char smem[];
    const uint32_t sb = smem_u32(smem);
    const int tid = threadIdx.x;
    const int lane = tid & 31, warp = tid >> 5;
    const int m0 = blockIdx.x * BM;
    const int n0 = blockIdx.y * BN;
    const int b = n0 >> 10;
    const int pix0 = n0 & (NPIX_ - 1);

    const uint32_t mbarA[2] = { sb + MBAR0_OFF, sb + MBAR1_OFF };
    if (tid == 0) {
        mbar_init(mbarA[0], 1);
        mbar_init(mbarA[1], 1);
    }
    asm volatile("fence.proxy.async.shared::cta;" ::: "memory");
    __syncthreads();

    // Per-thread B pixel
    const int pixL = pix0 + tid;
    const int ohL = pixL >> 5, owL = pixL & 31;
    const float* gX0 = g_Xf + (size_t)b * HW_ * CIN_;

    auto load_stage = [&](int buf, int s) {
        const int p = s >> 2;
        const int cin0 = (s & 3) * KC;
        const int kh = p / 3, kw = p - kh * 3;
        const uint32_t st = sb + TILES_OFF + buf * STAGE_B;
        const uint32_t mb = mbarA[buf];
        if (tid == 0) {
            int invalid = (kw == 0 ? 8 : 0)
                        + ((kh == 0 && pix0 == 0) ? 32 : 0)
                        - ((kw == 0 && kh == 0 && pix0 == 0) ? 1 : 0);
            uint32_t tx = 32768u + 256u * (uint32_t)(256 - invalid);
            mbar_expect_tx(mb, tx);
        }
        if (tid < 128) {
            const float* srcA = g_A3 + (size_t)p * (COUT_ * CIN_)
                              + (size_t)(m0 + tid) * CIN_ + cin0;
            bulk_g2s(st + tid * A_ROW_B, srcA, 256, mb);
        }
        const int ih = ohL * 2 - 1 + kh;
        const int iw = owL * 2 - 1 + kw;
        const uint32_t dst = st + OFF_B + tid * B_ROW_B;
        if (((unsigned)ih < (unsigned)H_) && ((unsigned)iw < (unsigned)W_)) {
            bulk_g2s(dst, gX0 + (size_t)(ih * W_ + iw) * CIN_ + cin0, 256, mb);
        } else {
#pragma unroll
            for (int j = 0; j < 16; ++j)
                asm volatile("st.shared.v4.b32 [%0], {%1, %1, %1, %1};"
                             :: "r"(dst + j * 16), "r"(0u) : "memory");
        }
    };

    float acc[4][8][4];
#pragma unroll
    for (int mi = 0; mi < 4; ++mi)
#pragma unroll
        for (int ni = 0; ni < 8; ++ni)
#pragma unroll
            for (int j = 0; j < 4; ++j) acc[mi][ni][j] = 0.0f;

    load_stage(0, 0);
    load_stage(1, 1);
    __syncthreads();   // make zero-STS of initial stages visible to all warps

    const int mw = (warp >> 2) * 64;
    const int nw = (warp & 3) * 64;
    const int lg = lane >> 2;
    const int lc = lane & 3;

#pragma unroll 1
    for (int it = 0; it < NIT; ++it) {
        mbar_wait(mbarA[it & 1], (it >> 1) & 1);
        const uint32_t st = sb + TILES_OFF + (it & 1) * STAGE_B;
        const uint32_t stB = st + OFF_B;
#pragma unroll
        for (int ks = 0; ks < 8; ++ks) {
            const uint32_t kbyte = (uint32_t)(ks * 8 + lc) * 4;
            uint32_t a[4][4];
#pragma unroll
            for (int mi = 0; mi < 4; ++mi) {
                const uint32_t r0 = st + (mw + mi * 16 + lg) * A_ROW_B + kbyte;
                a[mi][0] = lds32(r0);
                a[mi][1] = lds32(r0 + 8 * A_ROW_B);
                a[mi][2] = lds32(r0 + 16);
                a[mi][3] = lds32(r0 + 8 * A_ROW_B + 16);
            }
#pragma unroll
            for (int ni = 0; ni < 8; ++ni) {
                const uint32_t r0 = stB + (nw + ni * 8 + lg) * B_ROW_B + kbyte;
                uint32_t b0 = lds32(r0);
                uint32_t b1 = lds32(r0 + 16);
#pragma unroll
                for (int mi = 0; mi < 4; ++mi)
                    mma_tf32(acc[mi][ni], a[mi], b0, b1);
            }
        }
        __syncthreads();                       // all warps done with this buffer
        if (it + 2 < NIT) load_stage(it & 1, it + 2);
    }

    // ---- epilogue ----
    float* ob = out + (size_t)b * COUT_ * NPIX_;
#pragma unroll
    for (int mi = 0; mi < 4; ++mi) {
        const int cout0 = m0 + mw + mi * 16 + lg;
#pragma unroll
        for (int ni = 0; ni < 8; ++ni) {
            const int nc = pix0 + nw + ni * 8 + lc * 2;
            float2* p0 = (float2*)(ob + (size_t)cout0 * NPIX_ + nc);
            float2* p1 = (float2*)(ob + (size_t)(cout0 + 8) * NPIX_ + nc);
            *p0 = make_float2(acc[mi][ni][0], acc[mi][ni][1]);
            *p1 = make_float2(acc[mi][ni][2], acc[mi][ni][3]);
        }
    }
}

// ---------------------------------------------------------------------------
extern "C" void kernel_launch(void* const* d_in, const int* in_sizes, int n_in,
                              void* d_out, int out_size) {
    const float* x = (const float*)d_in[0];   // [32,256,64,64]
    const float* w = (const float*)d_in[1];   // [256,256,3,3]
    float* out = (float*)d_out;               // [32,256,32,32]

    cudaFuncSetAttribute(conv_tf32_kernel,
                         cudaFuncAttributeMaxDynamicSharedMemorySize, SMEM_TOTAL);

    {
        const int total = 9 * COUT_ * CIN_;
        weight_transform_kernel<<<(total + 255) / 256, 256>>>(w);
    }
    {
        dim3 blk(32, 8);
        dim3 grd(HW_ / 32, CIN_ / 32, B_);
        x_transform_kernel<<<grd, blk>>>(x);
    }
    {
        dim3 grid(COUT_ / BM, (B_ * NPIX_) / BN);   // (2, 128)
        conv_tf32_kernel<<<grid, 256, SMEM_TOTAL>>>(out);
    }
}

// round 6
// speedup vs baseline: 4.0372x; 1.1377x over previous
#include <cuda_runtime.h>
#include <cuda_bf16.h>
#include <cstdint>

// ---------------------------------------------------------------------------
// B=32, CIN=256, COUT=256, 64x64 -> 32x32, 3x3 stride2 pad1 conv. Crop mask
// all-True => plain conv. TF32 implicit GEMM on mma.sync.m16n8k8.
// Round 6: 512 threads (4 warps/SMSP) to hide LDS->HMMA latency; bulk-copy
// double-buffered pipeline unchanged.
// ---------------------------------------------------------------------------

#define B_    32
#define CIN_  256
#define COUT_ 256
#define H_    64
#define W_    64
#define HW_   4096
#define NPIX_ 1024

#define BM 128
#define BN 256
#define KC 64
#define NIT 36                 // 9 taps * 4 cin-chunks

#define A_ROW_B   272
#define A_TILE_B  (128 * A_ROW_B)          // 34816
#define B_ROW_B   272
#define B_TILE_B  (256 * B_ROW_B)          // 69632
#define STAGE_B   (A_TILE_B + B_TILE_B)    // 104448
#define OFF_B     A_TILE_B
#define TILES_OFF 1024
#define SMEM_TOTAL (TILES_OFF + 2 * STAGE_B)   // 209920
#define MBAR0_OFF 0
#define MBAR1_OFF 16

__device__ __align__(128) float g_A3[9 * COUT_ * CIN_];        // [p][cout][cin]
__device__ __align__(128) float g_Xf[(size_t)B_ * HW_ * CIN_]; // [b][s][cin]

// ---------------------------------------------------------------------------
__device__ __forceinline__ uint32_t smem_u32(const void* p) {
    uint32_t a;
    asm("{ .reg .u64 t; cvta.to.shared.u64 t, %1; cvt.u32.u64 %0, t; }" : "=r"(a) : "l"(p));
    return a;
}
__device__ __forceinline__ void bulk_g2s(uint32_t dst, const void* src, uint32_t bytes,
                                         uint32_t mbar) {
    asm volatile(
        "cp.async.bulk.shared::cluster.global.mbarrier::complete_tx::bytes "
        "[%0], [%1], %2, [%3];"
        :: "r"(dst), "l"(src), "r"(bytes), "r"(mbar) : "memory");
}
__device__ __forceinline__ void mbar_init(uint32_t a, uint32_t cnt) {
    asm volatile("mbarrier.init.shared.b64 [%0], %1;" :: "r"(a), "r"(cnt) : "memory");
}
__device__ __forceinline__ void mbar_expect_tx(uint32_t a, uint32_t tx) {
    asm volatile("mbarrier.arrive.expect_tx.shared.b64 _, [%0], %1;"
                 :: "r"(a), "r"(tx) : "memory");
}
__device__ __forceinline__ void mbar_wait(uint32_t a, uint32_t parity) {
    asm volatile(
        "{\n\t.reg .pred P1;\n\t"
        "W_%=:\n\t"
        "mbarrier.try_wait.parity.acquire.cta.shared::cta.b64 P1, [%0], %1, 0x989680;\n\t"
        "@!P1 bra W_%=;\n\t}"
        :: "r"(a), "r"(parity) : "memory");
}
__device__ __forceinline__ uint32_t f2tf32(float v) {
    uint32_t r;
    asm("cvt.rna.tf32.f32 %0, %1;" : "=r"(r) : "f"(v));
    return r;
}
__device__ __forceinline__ void mma_tf32(float* d, const uint32_t* a, uint32_t b0, uint32_t b1) {
    asm volatile(
        "mma.sync.aligned.m16n8k8.row.col.f32.tf32.tf32.f32 "
        "{%0,%1,%2,%3}, {%4,%5,%6,%7}, {%8,%9}, {%0,%1,%2,%3};"
        : "+f"(d[0]), "+f"(d[1]), "+f"(d[2]), "+f"(d[3])
        : "r"(a[0]), "r"(a[1]), "r"(a[2]), "r"(a[3]), "r"(b0), "r"(b1));
}
__device__ __forceinline__ uint32_t lds32(uint32_t addr) {
    uint32_t v;
    asm volatile("ld.shared.b32 %0, [%1];" : "=r"(v) : "r"(addr));
    return v;
}

// ---------------------------------------------------------------------------
// Prologues
// ---------------------------------------------------------------------------
__global__ void weight_transform_kernel(const float* __restrict__ w) {
    int idx = blockIdx.x * blockDim.x + threadIdx.x;
    const int total = 9 * COUT_ * CIN_;
    if (idx >= total) return;
    int cin = idx & 255;
    int cout = (idx >> 8) & 255;
    int p = idx >> 16;
    float v = w[cout * (CIN_ * 9) + cin * 9 + p];
    ((uint32_t*)g_A3)[idx] = f2tf32(v);
}

__global__ void x_transform_kernel(const float* __restrict__ x) {
    __shared__ float tile[32][33];
    int b = blockIdx.z, c0 = blockIdx.y * 32, s0 = blockIdx.x * 32;
    int tx = threadIdx.x, ty = threadIdx.y;        // 32 x 8
    const float* xb = x + ((size_t)b * CIN_ + c0) * HW_ + s0;
#pragma unroll
    for (int k = 0; k < 4; ++k)
        tile[ty + 8 * k][tx] = xb[(size_t)(ty + 8 * k) * HW_ + tx];
    __syncthreads();
#pragma unroll
    for (int k = 0; k < 4; ++k) {
        float v = tile[tx][ty + 8 * k];
        size_t o = ((size_t)b * HW_ + s0 + ty + 8 * k) * CIN_ + c0 + tx;
        ((uint32_t*)g_Xf)[o] = f2tf32(v);
    }
}

// ---------------------------------------------------------------------------
// Main TF32 implicit-GEMM. grid (2, 128), 512 threads (16 warps, 4/SMSP).
// Warp tile 32x64: 4 m-warp-groups x 4 n-warp-groups.
// ---------------------------------------------------------------------------
__global__ void __launch_bounds__(512, 1) conv_tf32_kernel(float* __restrict__ out) {
    extern __shared__ char smem[];
    const uint32_t sb = smem_u32(smem);
    const int tid = threadIdx.x;
    const int lane = tid & 31, warp = tid >> 5;
    const int m0 = blockIdx.x * BM;
    const int n0 = blockIdx.y * BN;
    const int b = n0 >> 10;
    const int pix0 = n0 & (NPIX_ - 1);

    const uint32_t mbarA[2] = { sb + MBAR0_OFF, sb + MBAR1_OFF };
    if (tid == 0) {
        mbar_init(mbarA[0], 1);
        mbar_init(mbarA[1], 1);
    }
    asm volatile("fence.proxy.async.shared::cta;" ::: "memory");
    __syncthreads();

    // B-row loader pixel (threads 0..255 handle B rows)
    const int pixL = pix0 + (tid & 255);
    const int ohL = pixL >> 5, owL = pixL & 31;
    const float* gX0 = g_Xf + (size_t)b * HW_ * CIN_;

    auto load_stage = [&](int buf, int s) {
        const int p = s >> 2;
        const int cin0 = (s & 3) * KC;
        const int kh = p / 3, kw = p - kh * 3;
        const uint32_t st = sb + TILES_OFF + buf * STAGE_B;
        const uint32_t mb = mbarA[buf];
        if (tid == 0) {
            int invalid = (kw == 0 ? 8 : 0)
                        + ((kh == 0 && pix0 == 0) ? 32 : 0)
                        - ((kw == 0 && kh == 0 && pix0 == 0) ? 1 : 0);
            uint32_t tx = 32768u + 256u * (uint32_t)(256 - invalid);
            mbar_expect_tx(mb, tx);
        }
        if (tid < 128) {
            const float* srcA = g_A3 + (size_t)p * (COUT_ * CIN_)
                              + (size_t)(m0 + tid) * CIN_ + cin0;
            bulk_g2s(st + tid * A_ROW_B, srcA, 256, mb);
        }
        if (tid < 256) {
            const int ih = ohL * 2 - 1 + kh;
            const int iw = owL * 2 - 1 + kw;
            const uint32_t dst = st + OFF_B + tid * B_ROW_B;
            if (((unsigned)ih < (unsigned)H_) && ((unsigned)iw < (unsigned)W_)) {
                bulk_g2s(dst, gX0 + (size_t)(ih * W_ + iw) * CIN_ + cin0, 256, mb);
            } else {
#pragma unroll
                for (int j = 0; j < 16; ++j)
                    asm volatile("st.shared.v4.b32 [%0], {%1, %1, %1, %1};"
                                 :: "r"(dst + j * 16), "r"(0u) : "memory");
            }
        }
    };

    float acc[2][8][4];
#pragma unroll
    for (int mi = 0; mi < 2; ++mi)
#pragma unroll
        for (int ni = 0; ni < 8; ++ni)
#pragma unroll
            for (int j = 0; j < 4; ++j) acc[mi][ni][j] = 0.0f;

    load_stage(0, 0);
    load_stage(1, 1);
    __syncthreads();   // zero-STS of initial stages visible to all warps

    const int mw = (warp >> 2) * 32;      // 0,32,64,96
    const int nw = (warp & 3) * 64;       // 0,64,128,192
    const int lg = lane >> 2;             // 0..7
    const int lc = lane & 3;              // 0..3

#pragma unroll 1
    for (int it = 0; it < NIT; ++it) {
        mbar_wait(mbarA[it & 1], (it >> 1) & 1);
        const uint32_t st = sb + TILES_OFF + (it & 1) * STAGE_B;
        const uint32_t stB = st + OFF_B;
#pragma unroll
        for (int ks = 0; ks < 8; ++ks) {
            const uint32_t kbyte = (uint32_t)(ks * 8 + lc) * 4;
            uint32_t a[2][4];
#pragma unroll
            for (int mi = 0; mi < 2; ++mi) {
                const uint32_t r0 = st + (mw + mi * 16 + lg) * A_ROW_B + kbyte;
                a[mi][0] = lds32(r0);
                a[mi][1] = lds32(r0 + 8 * A_ROW_B);
                a[mi][2] = lds32(r0 + 16);
                a[mi][3] = lds32(r0 + 8 * A_ROW_B + 16);
            }
#pragma unroll
            for (int ni = 0; ni < 8; ++ni) {
                const uint32_t r0 = stB + (nw + ni * 8 + lg) * B_ROW_B + kbyte;
                uint32_t b0 = lds32(r0);
                uint32_t b1 = lds32(r0 + 16);
#pragma unroll
                for (int mi = 0; mi < 2; ++mi)
                    mma_tf32(acc[mi][ni], a[mi], b0, b1);
            }
        }
        __syncthreads();                       // all warps done with this buffer
        if (it + 2 < NIT) load_stage(it & 1, it + 2);
    }

    // ---- epilogue ----
    float* ob = out + (size_t)b * COUT_ * NPIX_;
#pragma unroll
    for (int mi = 0; mi < 2; ++mi) {
        const int cout0 = m0 + mw + mi * 16 + lg;
#pragma unroll
        for (int ni = 0; ni < 8; ++ni) {
            const int nc = pix0 + nw + ni * 8 + lc * 2;
            float2* p0 = (float2*)(ob + (size_t)cout0 * NPIX_ + nc);
            float2* p1 = (float2*)(ob + (size_t)(cout0 + 8) * NPIX_ + nc);
            *p0 = make_float2(acc[mi][ni][0], acc[mi][ni][1]);
            *p1 = make_float2(acc[mi][ni][2], acc[mi][ni][3]);
        }
    }
}

// ---------------------------------------------------------------------------
extern "C" void kernel_launch(void* const* d_in, const int* in_sizes, int n_in,
                              void* d_out, int out_size) {
    const float* x = (const float*)d_in[0];   // [32,256,64,64]
    const float* w = (const float*)d_in[1];   // [256,256,3,3]
    float* out = (float*)d_out;               // [32,256,32,32]

    cudaFuncSetAttribute(conv_tf32_kernel,
                         cudaFuncAttributeMaxDynamicSharedMemorySize, SMEM_TOTAL);

    {
        const int total = 9 * COUT_ * CIN_;
        weight_transform_kernel<<<(total + 255) / 256, 256>>>(w);
    }
    {
        dim3 blk(32, 8);
        dim3 grd(HW_ / 32, CIN_ / 32, B_);
        x_transform_kernel<<<grd, blk>>>(x);
    }
    {
        dim3 grid(COUT_ / BM, (B_ * NPIX_) / BN);   // (2, 128)
        conv_tf32_kernel<<<grid, 512, SMEM_TOTAL>>>(out);
    }
}